// round 8
// baseline (speedup 1.0000x reference)
#include <cuda_runtime.h>
#include <cuda_bf16.h>

#define TSEQ 2048
#define HDIM 2048
#define DDIM 512
#define ODIM 512
#define NCTA 147
#define UPC  14
#define NROWS 56
#define REG_ROWS 24
#define SM_ROWS 30          // rows 24..53 in SMEM
// SMEM: 30*1024 u32 weights + zpart[2][56*8] + hsm[8*256]
#define SMEM_BYTES (SM_ROWS * 1024 * 4 + 2 * NROWS * 8 * 4 + 8 * 256 * 4)

// ---------------- scratch (device globals; no allocation) ----------------
__device__ float  g_xproj[(size_t)TSEQ * 4 * HDIM];
__device__ float  g_ys0[(size_t)TSEQ * HDIM];
__device__ float  g_ys1[(size_t)TSEQ * HDIM];
__device__ float4 g_hbuf0[(size_t)TSEQ * NCTA * 5];   // {h,h,h,tag}
__device__ float4 g_hbuf1[(size_t)TSEQ * NCTA * 5];

__global__ void zero_hbuf_kernel() {
    size_t n = (size_t)TSEQ * NCTA * 5;
    float4 z = make_float4(0.f, 0.f, 0.f, 0.f);
    for (size_t i = blockIdx.x * blockDim.x + threadIdx.x; i < n;
         i += (size_t)gridDim.x * blockDim.x) {
        g_hbuf0[i] = z;
        g_hbuf1[i] = z;
    }
}

// ---------------- helpers ----------------
__device__ __forceinline__ float4 ldcg_v4(const float4* p) {
    float4 v;
    asm volatile("ld.global.cg.v4.f32 {%0,%1,%2,%3}, [%4];"
                 : "=f"(v.x), "=f"(v.y), "=f"(v.z), "=f"(v.w) : "l"(p));
    return v;
}
__device__ __forceinline__ void stcg_v4(float4* p, float a, float b, float c, float d) {
    asm volatile("st.global.cg.v4.f32 [%0], {%1,%2,%3,%4};"
                 :: "l"(p), "f"(a), "f"(b), "f"(c), "f"(d) : "memory");
}
__device__ __forceinline__ float htanh(float x) {
    float r;
    asm("tanh.approx.f32 %0, %1;" : "=f"(r) : "f"(x));
    return r;
}
__device__ __forceinline__ float fsig(float x) {
    return fmaf(0.5f, htanh(0.5f * x), 0.5f);
}
__device__ __forceinline__ float merge2(float a, float b, int m, int lane) {
    bool hi = (lane & m) != 0;
    float mine = hi ? b : a;
    float theirs = hi ? a : b;
    return mine + __shfl_xor_sync(0xffffffffu, theirs, m);
}
// Compensated pack: low 16 = bf16(w_even); whole u32 read as f32 is the
// nearest value to w_odd on lattice {k*2^16 + lo} (error <= half bf16 ulp).
__device__ __forceinline__ unsigned pack_comp(float we, float wo) {
    unsigned lo = (unsigned)__bfloat16_as_ushort(__float2bfloat16_rn(we));
    unsigned ob = __float_as_uint(wo);
    unsigned hi = (ob >= 0x10000u) ? ((ob - lo + 0x8000u) >> 16) : (ob >> 16);
    return (hi << 16) | lo;
}
// f32x2 packed ops (sm_103a)
#define PK64(d, lo, hi) \
    asm("mov.b64 %0, {%1, %2};" : "=l"(d) : "r"(lo), "r"(hi))
#define PK64F(d, lo, hi) \
    asm("mov.b64 %0, {%1, %2};" : "=l"(d) : "f"(lo), "f"(hi))
#define MUL2(d, a, b) \
    asm("mul.rn.f32x2 %0, %1, %2;" : "=l"(d) : "l"(a), "l"(b))
#define FMA2(d, a, b, c) \
    asm("fma.rn.f32x2 %0, %1, %2, %3;" : "=l"(d) : "l"(a), "l"(b), "l"(c))
#define UNPK(lo, hi, s) \
    asm("mov.b64 {%0, %1}, %2;" : "=f"(lo), "=f"(hi) : "l"(s))

// ---------------- GEMM: C[m][n] = sum_k A[m][k]*B[n][k] + b1[n] + b2[n] ----
#define BM 128
#define BN 128
#define BK 16

__global__ void __launch_bounds__(256, 2) gemm_bias_kernel(
    const float* __restrict__ A, const float* __restrict__ B,
    const float* __restrict__ bias1, const float* __restrict__ bias2,
    float* __restrict__ C, int M, int N, int K)
{
    __shared__ float As[BK][BM + 4];
    __shared__ float Bs[BK][BN + 4];
    const int tid = threadIdx.x;
    const int tx = tid & 15;
    const int ty = tid >> 4;
    const int m0 = blockIdx.y * BM;
    const int n0 = blockIdx.x * BN;
    const int lrow = tid >> 2;
    const int lk4  = (tid & 3) * 4;

    const float* Aptr0 = A + (size_t)(m0 + lrow) * K + lk4;
    const float* Aptr1 = A + (size_t)(m0 + lrow + 64) * K + lk4;
    const float* Bptr0 = B + (size_t)(n0 + lrow) * K + lk4;
    const float* Bptr1 = B + (size_t)(n0 + lrow + 64) * K + lk4;

    float4 ra0 = *(const float4*)(Aptr0);
    float4 ra1 = *(const float4*)(Aptr1);
    float4 rb0 = *(const float4*)(Bptr0);
    float4 rb1 = *(const float4*)(Bptr1);

    float acc[8][8];
#pragma unroll
    for (int i = 0; i < 8; ++i)
#pragma unroll
        for (int j = 0; j < 8; ++j) acc[i][j] = 0.0f;

    for (int k0 = 0; k0 < K; k0 += BK) {
        As[lk4 + 0][lrow] = ra0.x; As[lk4 + 1][lrow] = ra0.y;
        As[lk4 + 2][lrow] = ra0.z; As[lk4 + 3][lrow] = ra0.w;
        As[lk4 + 0][lrow + 64] = ra1.x; As[lk4 + 1][lrow + 64] = ra1.y;
        As[lk4 + 2][lrow + 64] = ra1.z; As[lk4 + 3][lrow + 64] = ra1.w;
        Bs[lk4 + 0][lrow] = rb0.x; Bs[lk4 + 1][lrow] = rb0.y;
        Bs[lk4 + 2][lrow] = rb0.z; Bs[lk4 + 3][lrow] = rb0.w;
        Bs[lk4 + 0][lrow + 64] = rb1.x; Bs[lk4 + 1][lrow + 64] = rb1.y;
        Bs[lk4 + 2][lrow + 64] = rb1.z; Bs[lk4 + 3][lrow + 64] = rb1.w;
        __syncthreads();

        if (k0 + BK < K) {
            ra0 = *(const float4*)(Aptr0 + k0 + BK);
            ra1 = *(const float4*)(Aptr1 + k0 + BK);
            rb0 = *(const float4*)(Bptr0 + k0 + BK);
            rb1 = *(const float4*)(Bptr1 + k0 + BK);
        }

#pragma unroll
        for (int kk = 0; kk < BK; ++kk) {
            float4 a0 = *(const float4*)&As[kk][ty * 4];
            float4 a1 = *(const float4*)&As[kk][64 + ty * 4];
            float4 b0 = *(const float4*)&Bs[kk][tx * 4];
            float4 b1 = *(const float4*)&Bs[kk][64 + tx * 4];
            float av[8] = {a0.x, a0.y, a0.z, a0.w, a1.x, a1.y, a1.z, a1.w};
            float bv[8] = {b0.x, b0.y, b0.z, b0.w, b1.x, b1.y, b1.z, b1.w};
#pragma unroll
            for (int i = 0; i < 8; ++i)
#pragma unroll
                for (int j = 0; j < 8; ++j)
                    acc[i][j] = fmaf(av[i], bv[j], acc[i][j]);
        }
        __syncthreads();
    }

    float bs[8];
#pragma unroll
    for (int j = 0; j < 8; ++j) {
        int n = n0 + ((j < 4) ? (tx * 4 + j) : (64 + tx * 4 + (j - 4)));
        bs[j] = bias1[n] + bias2[n];
    }
#pragma unroll
    for (int i = 0; i < 8; ++i) {
        int m = m0 + ((i < 4) ? (ty * 4 + i) : (64 + ty * 4 + (i - 4)));
        float4 v0 = make_float4(acc[i][0] + bs[0], acc[i][1] + bs[1],
                                acc[i][2] + bs[2], acc[i][3] + bs[3]);
        float4 v1 = make_float4(acc[i][4] + bs[4], acc[i][5] + bs[5],
                                acc[i][6] + bs[6], acc[i][7] + bs[7]);
        *(float4*)(C + (size_t)m * N + n0 + tx * 4) = v0;
        *(float4*)(C + (size_t)m * N + n0 + 64 + tx * 4) = v1;
    }
}

// ---------------- persistent LSTM recurrence ----------------
__global__ void __launch_bounds__(256, 1) lstm_layer_kernel(
    const float* __restrict__ Whh, const float* __restrict__ xproj,
    float* __restrict__ ys, float4* __restrict__ hbuf)
{
    extern __shared__ unsigned int smem_u[];
    unsigned int* wsm = smem_u;                           // rows 24..53
    float* zpart = (float*)(smem_u + SM_ROWS * 1024);     // [2][56][8]
    float* hsm = zpart + 2 * NROWS * 8;                   // [8][256]

    const int tid = threadIdx.x;
    const int cta = blockIdx.x;
    const int u0 = cta * UPC;
    const int nu = min(UPC, HDIM - u0);
    const int lane = tid & 31;
    const int wid = tid >> 5;
    const int dbase = wid * 256 + lane * 8;

    // SMEM weights rows 24..53, compensated-packed, ghost clamp.
    for (int idx = tid; idx < SM_ROWS * 1024; idx += 256) {
        int r = (idx >> 10) + 24;
        int c2 = idx & 1023;
        int g = r / UPC;
        int u = r - g * UPC;
        int urow = min(u0 + u, HDIM - 1);
        const float* wrow = Whh + (size_t)(g * HDIM + urow) * HDIM;
        float2 w = *(const float2*)(wrow + 2 * c2);
        wsm[idx] = pack_comp(w.x, w.y);
    }

    // Rows 0..23 in registers: u64 pairs of packed u32.
    unsigned long long wr01[REG_ROWS], wr23[REG_ROWS];
#pragma unroll
    for (int r = 0; r < REG_ROWS; ++r) {
        int g = r / UPC;
        int u = r - g * UPC;
        int urow = min(u0 + u, HDIM - 1);
        const float* wrow = Whh + (size_t)(g * HDIM + urow) * HDIM + dbase;
        float4 wa = *(const float4*)(wrow);
        float4 wb = *(const float4*)(wrow + 4);
        unsigned p0 = pack_comp(wa.x, wa.y);
        unsigned p1 = pack_comp(wa.z, wa.w);
        unsigned p2 = pack_comp(wb.x, wb.y);
        unsigned p3 = pack_comp(wb.z, wb.w);
        PK64(wr01[r], p0, p1);
        PK64(wr23[r], p2, p3);
    }

    // Rows 54 (g3,u12), 55 (g3,u13): full fp32 as f32x2 pairs.
    unsigned long long wA54, wB54, wC54, wD54, wA55, wB55, wC55, wD55;
    {
        const float* p54 = Whh + ((size_t)3 * HDIM + min(u0 + 12, HDIM - 1)) * HDIM + dbase;
        const float* p55 = Whh + ((size_t)3 * HDIM + min(u0 + 13, HDIM - 1)) * HDIM + dbase;
        PK64F(wA54, p54[0], p54[2]); PK64F(wB54, p54[1], p54[3]);
        PK64F(wC54, p54[4], p54[6]); PK64F(wD54, p54[5], p54[7]);
        PK64F(wA55, p55[0], p55[2]); PK64F(wB55, p55[1], p55[3]);
        PK64F(wC55, p55[4], p55[6]); PK64F(wD55, p55[5], p55[7]);
    }

    // Gather plan
    const int c0 = (wid * 256) / UPC;
    const int c1 = (wid * 256 + 255) / UPC;
    const int nv = (c1 - c0 + 1) * 5;
    int psrc[4], pdst[4], pnc[4];
    bool pval[4];
#pragma unroll
    for (int p = 0; p < 4; ++p) {
        int v = p * 32 + lane;
        pval[p] = v < nv;
        int vc = pval[p] ? v : 0;
        int b = c0 + vc / 5;
        int vi = vc - (vc / 5) * 5;
        psrc[p] = b * 5 + vi;
        pdst[p] = b * UPC + 3 * vi - wid * 256;
        pnc[p] = (vi == 4) ? 2 : 3;
    }
    __syncthreads();

    const int krev = ((lane >> 4) & 1) | (((lane >> 3) & 1) << 1) | (((lane >> 2) & 1) << 2);
    const unsigned int* wbase = wsm + wid * 128 + lane * 4;   // SMEM row k-slice
    float cstate = 0.0f;

    for (int t = 0; t < TSEQ; ++t) {
        float xp0 = 0.f, xp1 = 0.f, xp2 = 0.f, xp3 = 0.f;
        if (tid < nu) {
            const float* xp = xproj + (size_t)t * (4 * HDIM) + u0 + tid;
            xp0 = __ldcg(xp);
            xp1 = __ldcg(xp + HDIM);
            xp2 = __ldcg(xp + 2 * HDIM);
            xp3 = __ldcg(xp + 3 * HDIM);
        }
        float* zbuf = zpart + (t & 1) * (NROWS * 8);

        if (t > 0) {
            // poll tagged vectors of step t-1; recheck only pending ones
            const float4* hb = hbuf + (size_t)(t - 1) * (NCTA * 5);
            float4 gv0, gv1, gv2, gv3;
            bool d0 = !pval[0], d1 = !pval[1], d2 = !pval[2], d3 = !pval[3];
            for (;;) {
                if (!d0) { gv0 = ldcg_v4(hb + psrc[0]); d0 = (__float_as_int(gv0.w) == t); }
                if (!d1) { gv1 = ldcg_v4(hb + psrc[1]); d1 = (__float_as_int(gv1.w) == t); }
                if (!d2) { gv2 = ldcg_v4(hb + psrc[2]); d2 = (__float_as_int(gv2.w) == t); }
                if (!d3) { gv3 = ldcg_v4(hb + psrc[3]); d3 = (__float_as_int(gv3.w) == t); }
                if (__all_sync(0xffffffffu, d0 && d1 && d2 && d3)) break;
            }
            float* hw = hsm + wid * 256;
#pragma unroll
            for (int p = 0; p < 4; ++p) {
                if (pval[p]) {
                    float4 g = (p == 0) ? gv0 : (p == 1) ? gv1 : (p == 2) ? gv2 : gv3;
                    int i0 = pdst[p];
                    if ((unsigned)i0 < 256u) hw[i0] = g.x;
                    if ((unsigned)(i0 + 1) < 256u) hw[i0 + 1] = g.y;
                    if (pnc[p] == 3 && (unsigned)(i0 + 2) < 256u) hw[i0 + 2] = g.z;
                }
            }
            __syncwarp();
            float4 ha = *(const float4*)(hw + lane * 8);
            float4 hbv = *(const float4*)(hw + lane * 8 + 4);
            // h pairs: {h0,h2},{h1,h3},{h4,h6},{h5,h7}
            unsigned long long h02, h13, h46, h57;
            PK64F(h02, ha.x, ha.z);  PK64F(h13, ha.y, ha.w);
            PK64F(h46, hbv.x, hbv.z); PK64F(h57, hbv.y, hbv.w);

            // 7 groups of 8 rows; per row 6 fma-pipe slots via f32x2
#pragma unroll
            for (int g = 0; g < 7; ++g) {
                float acc[8];
#pragma unroll
                for (int j = 0; j < 8; ++j) {
                    int r = 8 * g + j;
                    float lo, hi;
                    if (r < REG_ROWS) {
                        unsigned long long A01 = wr01[r], A23 = wr23[r];
                        unsigned e0 = (unsigned)A01 << 16;
                        unsigned e1 = (unsigned)(A01 >> 32) << 16;
                        unsigned e2 = (unsigned)A23 << 16;
                        unsigned e3 = (unsigned)(A23 >> 32) << 16;
                        unsigned long long E01, E23, pe, po;
                        PK64(E01, e0, e1); PK64(E23, e2, e3);
                        MUL2(pe, E01, h02); FMA2(pe, E23, h46, pe);
                        MUL2(po, A01, h13); FMA2(po, A23, h57, po);
                        FMA2(pe, po, 0x3F8000003F800000ULL, pe); // po*{1,1}+pe
                        UNPK(lo, hi, pe);
                        acc[j] = lo + hi;
                    } else if (r < 54) {
                        const ulonglong2* wp = (const ulonglong2*)(wbase + (r - 24) * 1024);
                        ulonglong2 W = *wp;
                        unsigned long long A01 = W.x, A23 = W.y;
                        unsigned e0 = (unsigned)A01 << 16;
                        unsigned e1 = (unsigned)(A01 >> 32) << 16;
                        unsigned e2 = (unsigned)A23 << 16;
                        unsigned e3 = (unsigned)(A23 >> 32) << 16;
                        unsigned long long E01, E23, pe, po;
                        PK64(E01, e0, e1); PK64(E23, e2, e3);
                        MUL2(pe, E01, h02); FMA2(pe, E23, h46, pe);
                        MUL2(po, A01, h13); FMA2(po, A23, h57, po);
                        FMA2(pe, po, 0x3F8000003F800000ULL, pe);
                        UNPK(lo, hi, pe);
                        acc[j] = lo + hi;
                    } else {
                        unsigned long long wA = (r == 54) ? wA54 : wA55;
                        unsigned long long wB = (r == 54) ? wB54 : wB55;
                        unsigned long long wC = (r == 54) ? wC54 : wC55;
                        unsigned long long wD = (r == 54) ? wD54 : wD55;
                        unsigned long long p;
                        MUL2(p, wA, h02); FMA2(p, wB, h13, p);
                        FMA2(p, wC, h46, p); FMA2(p, wD, h57, p);
                        UNPK(lo, hi, p);
                        acc[j] = lo + hi;
                    }
                }
                float a0 = merge2(acc[0], acc[1], 16, lane);
                float a1 = merge2(acc[2], acc[3], 16, lane);
                float a2 = merge2(acc[4], acc[5], 16, lane);
                float a3 = merge2(acc[6], acc[7], 16, lane);
                float b0 = merge2(a0, a1, 8, lane);
                float b1 = merge2(a2, a3, 8, lane);
                float c0v = merge2(b0, b1, 4, lane);
                c0v += __shfl_xor_sync(0xffffffffu, c0v, 2);
                c0v += __shfl_xor_sync(0xffffffffu, c0v, 1);
                if ((lane & 3) == 0) zbuf[(8 * g + krev) * 8 + wid] = c0v;
            }
            __syncthreads();
        }

        // gate math + tagged publish (warp 0)
        if (wid == 0) {
            float hv = 0.0f;
            if (lane < nu) {
                float zi = xp0, zf = xp1, zg = xp2, zo = xp3;
                if (t > 0) {
                    const float4* z0 = (const float4*)(zbuf + (0 * UPC + lane) * 8);
                    const float4* z1 = (const float4*)(zbuf + (1 * UPC + lane) * 8);
                    const float4* z2 = (const float4*)(zbuf + (2 * UPC + lane) * 8);
                    const float4* z3 = (const float4*)(zbuf + (3 * UPC + lane) * 8);
                    float4 a, b;
                    a = z0[0]; b = z0[1];
                    zi += (a.x + a.y) + (a.z + a.w) + (b.x + b.y) + (b.z + b.w);
                    a = z1[0]; b = z1[1];
                    zf += (a.x + a.y) + (a.z + a.w) + (b.x + b.y) + (b.z + b.w);
                    a = z2[0]; b = z2[1];
                    zg += (a.x + a.y) + (a.z + a.w) + (b.x + b.y) + (b.z + b.w);
                    a = z3[0]; b = z3[1];
                    zo += (a.x + a.y) + (a.z + a.w) + (b.x + b.y) + (b.z + b.w);
                }
                float ig = fsig(zi);
                float fg = fsig(zf);
                float gg = htanh(zg);
                float og = fsig(zo);
                float c = fg * cstate + ig * gg;
                cstate = c;
                hv = og * htanh(c);
            }
            float pa = __shfl_sync(0xffffffffu, hv, (3 * lane) & 31);
            float pb = __shfl_sync(0xffffffffu, hv, (3 * lane + 1) & 31);
            float pc = __shfl_sync(0xffffffffu, hv, (3 * lane + 2) & 31);
            if (lane < 5)
                stcg_v4(hbuf + ((size_t)t * NCTA + cta) * 5 + lane,
                        pa, pb, pc, __int_as_float(t + 1));
            if (lane < nu)
                __stcg(ys + (size_t)t * HDIM + u0 + lane, hv);
        }
        // no trailing sync: zpart is double-buffered by (t&1)
    }
}

// ---------------- FC ----------------
__global__ void __launch_bounds__(256) fc_kernel(
    const float* __restrict__ hlast, const float* __restrict__ W,
    const float* __restrict__ bias, float* __restrict__ out)
{
    int o = blockIdx.x * 8 + (threadIdx.x >> 5);
    int lane = threadIdx.x & 31;
    const float* w = W + (size_t)o * HDIM;
    float s = 0.0f;
    for (int k = lane * 4; k < HDIM; k += 128) {
        float4 wv = *(const float4*)(w + k);
        float4 hv = *(const float4*)(hlast + k);
        s += wv.x * hv.x + wv.y * hv.y + wv.z * hv.z + wv.w * hv.w;
    }
    s += __shfl_xor_sync(0xffffffffu, s, 16);
    s += __shfl_xor_sync(0xffffffffu, s, 8);
    s += __shfl_xor_sync(0xffffffffu, s, 4);
    s += __shfl_xor_sync(0xffffffffu, s, 2);
    s += __shfl_xor_sync(0xffffffffu, s, 1);
    if (lane == 0) out[o] = s + bias[o];
}

// ---------------- launch ----------------
extern "C" void kernel_launch(void* const* d_in, const int* in_sizes, int n_in,
                              void* d_out, int out_size)
{
    const float* x    = (const float*)d_in[0];
    const float* Wih0 = (const float*)d_in[1];
    const float* Whh0 = (const float*)d_in[2];
    const float* bih0 = (const float*)d_in[3];
    const float* bhh0 = (const float*)d_in[4];
    const float* Wih1 = (const float*)d_in[5];
    const float* Whh1 = (const float*)d_in[6];
    const float* bih1 = (const float*)d_in[7];
    const float* bhh1 = (const float*)d_in[8];
    const float* fcw  = (const float*)d_in[9];
    const float* fcb  = (const float*)d_in[10];
    float* out = (float*)d_out;

    float *xproj, *ys0, *ys1;
    float4 *hb0, *hb1;
    cudaGetSymbolAddress((void**)&xproj, g_xproj);
    cudaGetSymbolAddress((void**)&ys0, g_ys0);
    cudaGetSymbolAddress((void**)&ys1, g_ys1);
    cudaGetSymbolAddress((void**)&hb0, g_hbuf0);
    cudaGetSymbolAddress((void**)&hb1, g_hbuf1);

    cudaFuncSetAttribute(lstm_layer_kernel,
                         cudaFuncAttributeMaxDynamicSharedMemorySize, SMEM_BYTES);

    zero_hbuf_kernel<<<592, 256>>>();

    dim3 ggrid((4 * HDIM) / BN, TSEQ / BM);
    gemm_bias_kernel<<<ggrid, 256>>>(x, Wih0, bih0, bhh0, xproj, TSEQ, 4 * HDIM, DDIM);
    lstm_layer_kernel<<<NCTA, 256, SMEM_BYTES>>>(Whh0, xproj, ys0, hb0);
    gemm_bias_kernel<<<ggrid, 256>>>(ys0, Wih1, bih1, bhh1, xproj, TSEQ, 4 * HDIM, HDIM);
    lstm_layer_kernel<<<NCTA, 256, SMEM_BYTES>>>(Whh1, xproj, ys1, hb1);
    fc_kernel<<<ODIM / 8, 256>>>(ys1 + (size_t)(TSEQ - 1) * HDIM, fcw, fcb, out);
}

// round 11
// speedup vs baseline: 1.2347x; 1.2347x over previous
#include <cuda_runtime.h>
#include <cuda_bf16.h>

#define TSEQ 2048
#define HDIM 2048
#define DDIM 512
#define ODIM 512
#define NCTA 147
#define UPC  14
#define NROWS 56
#define WSM_ROWS 53
// SMEM: 53*1024 u32 weights + zpart[2][56*8] + hsm[8*256] = 228864 <= 232448
#define SMEM_BYTES (WSM_ROWS * 1024 * 4 + 2 * NROWS * 8 * 4 + 8 * 256 * 4)

// ---------------- scratch (device globals; no allocation) ----------------
__device__ float  g_xproj[(size_t)TSEQ * 4 * HDIM];
__device__ float  g_ys0[(size_t)TSEQ * HDIM];
__device__ float  g_ys1[(size_t)TSEQ * HDIM];
__device__ float4 g_hbuf0[(size_t)TSEQ * NCTA * 5];   // {h,h,h,tag}
__device__ float4 g_hbuf1[(size_t)TSEQ * NCTA * 5];

__global__ void zero_hbuf_kernel() {
    size_t n = (size_t)TSEQ * NCTA * 5;
    float4 z = make_float4(0.f, 0.f, 0.f, 0.f);
    for (size_t i = blockIdx.x * blockDim.x + threadIdx.x; i < n;
         i += (size_t)gridDim.x * blockDim.x) {
        g_hbuf0[i] = z;
        g_hbuf1[i] = z;
    }
}

// ---------------- helpers ----------------
__device__ __forceinline__ float4 ldcg_v4(const float4* p) {
    float4 v;
    asm volatile("ld.global.cg.v4.f32 {%0,%1,%2,%3}, [%4];"
                 : "=f"(v.x), "=f"(v.y), "=f"(v.z), "=f"(v.w) : "l"(p));
    return v;
}
__device__ __forceinline__ void stcg_v4(float4* p, float a, float b, float c, float d) {
    asm volatile("st.global.cg.v4.f32 [%0], {%1,%2,%3,%4};"
                 :: "l"(p), "f"(a), "f"(b), "f"(c), "f"(d) : "memory");
}
__device__ __forceinline__ float htanh(float x) {
    float r;
    asm("tanh.approx.f32 %0, %1;" : "=f"(r) : "f"(x));
    return r;
}
__device__ __forceinline__ float fsig(float x) {
    return fmaf(0.5f, htanh(0.5f * x), 0.5f);
}
__device__ __forceinline__ float merge2(float a, float b, int m, int lane) {
    bool hi = (lane & m) != 0;
    float mine = hi ? b : a;
    float theirs = hi ? a : b;
    return mine + __shfl_xor_sync(0xffffffffu, theirs, m);
}
// Compensated pack: low 16 = bf16(w_even); whole u32 read as f32 is the
// nearest value to w_odd on lattice {k*2^16 + lo} (error <= half bf16 ulp).
__device__ __forceinline__ unsigned pack_comp(float we, float wo) {
    unsigned lo = (unsigned)__bfloat16_as_ushort(__float2bfloat16_rn(we));
    unsigned ob = __float_as_uint(wo);
    unsigned hi = (ob >= 0x10000u) ? ((ob - lo + 0x8000u) >> 16) : (ob >> 16);
    return (hi << 16) | lo;
}

// ---------------- GEMM: C[m][n] = sum_k A[m][k]*B[n][k] + b1[n] + b2[n] ----
#define BM 128
#define BN 128
#define BK 16

__global__ void __launch_bounds__(256, 2) gemm_bias_kernel(
    const float* __restrict__ A, const float* __restrict__ B,
    const float* __restrict__ bias1, const float* __restrict__ bias2,
    float* __restrict__ C, int M, int N, int K)
{
    __shared__ float As[BK][BM + 4];
    __shared__ float Bs[BK][BN + 4];
    const int tid = threadIdx.x;
    const int tx = tid & 15;
    const int ty = tid >> 4;
    const int m0 = blockIdx.y * BM;
    const int n0 = blockIdx.x * BN;
    const int lrow = tid >> 2;
    const int lk4  = (tid & 3) * 4;

    const float* Aptr0 = A + (size_t)(m0 + lrow) * K + lk4;
    const float* Aptr1 = A + (size_t)(m0 + lrow + 64) * K + lk4;
    const float* Bptr0 = B + (size_t)(n0 + lrow) * K + lk4;
    const float* Bptr1 = B + (size_t)(n0 + lrow + 64) * K + lk4;

    float4 ra0 = *(const float4*)(Aptr0);
    float4 ra1 = *(const float4*)(Aptr1);
    float4 rb0 = *(const float4*)(Bptr0);
    float4 rb1 = *(const float4*)(Bptr1);

    float acc[8][8];
#pragma unroll
    for (int i = 0; i < 8; ++i)
#pragma unroll
        for (int j = 0; j < 8; ++j) acc[i][j] = 0.0f;

    for (int k0 = 0; k0 < K; k0 += BK) {
        As[lk4 + 0][lrow] = ra0.x; As[lk4 + 1][lrow] = ra0.y;
        As[lk4 + 2][lrow] = ra0.z; As[lk4 + 3][lrow] = ra0.w;
        As[lk4 + 0][lrow + 64] = ra1.x; As[lk4 + 1][lrow + 64] = ra1.y;
        As[lk4 + 2][lrow + 64] = ra1.z; As[lk4 + 3][lrow + 64] = ra1.w;
        Bs[lk4 + 0][lrow] = rb0.x; Bs[lk4 + 1][lrow] = rb0.y;
        Bs[lk4 + 2][lrow] = rb0.z; Bs[lk4 + 3][lrow] = rb0.w;
        Bs[lk4 + 0][lrow + 64] = rb1.x; Bs[lk4 + 1][lrow + 64] = rb1.y;
        Bs[lk4 + 2][lrow + 64] = rb1.z; Bs[lk4 + 3][lrow + 64] = rb1.w;
        __syncthreads();

        if (k0 + BK < K) {
            ra0 = *(const float4*)(Aptr0 + k0 + BK);
            ra1 = *(const float4*)(Aptr1 + k0 + BK);
            rb0 = *(const float4*)(Bptr0 + k0 + BK);
            rb1 = *(const float4*)(Bptr1 + k0 + BK);
        }

#pragma unroll
        for (int kk = 0; kk < BK; ++kk) {
            float4 a0 = *(const float4*)&As[kk][ty * 4];
            float4 a1 = *(const float4*)&As[kk][64 + ty * 4];
            float4 b0 = *(const float4*)&Bs[kk][tx * 4];
            float4 b1 = *(const float4*)&Bs[kk][64 + tx * 4];
            float av[8] = {a0.x, a0.y, a0.z, a0.w, a1.x, a1.y, a1.z, a1.w};
            float bv[8] = {b0.x, b0.y, b0.z, b0.w, b1.x, b1.y, b1.z, b1.w};
#pragma unroll
            for (int i = 0; i < 8; ++i)
#pragma unroll
                for (int j = 0; j < 8; ++j)
                    acc[i][j] = fmaf(av[i], bv[j], acc[i][j]);
        }
        __syncthreads();
    }

    float bs[8];
#pragma unroll
    for (int j = 0; j < 8; ++j) {
        int n = n0 + ((j < 4) ? (tx * 4 + j) : (64 + tx * 4 + (j - 4)));
        bs[j] = bias1[n] + bias2[n];
    }
#pragma unroll
    for (int i = 0; i < 8; ++i) {
        int m = m0 + ((i < 4) ? (ty * 4 + i) : (64 + ty * 4 + (i - 4)));
        float4 v0 = make_float4(acc[i][0] + bs[0], acc[i][1] + bs[1],
                                acc[i][2] + bs[2], acc[i][3] + bs[3]);
        float4 v1 = make_float4(acc[i][4] + bs[4], acc[i][5] + bs[5],
                                acc[i][6] + bs[6], acc[i][7] + bs[7]);
        *(float4*)(C + (size_t)m * N + n0 + tx * 4) = v0;
        *(float4*)(C + (size_t)m * N + n0 + 64 + tx * 4) = v1;
    }
}

// ---------------- persistent LSTM recurrence (tagged publish) -------------
__global__ void __launch_bounds__(256, 1) lstm_layer_kernel(
    const float* __restrict__ Whh, const float* __restrict__ xproj,
    float* __restrict__ ys, float4* __restrict__ hbuf)
{
    extern __shared__ unsigned int smem_u[];
    unsigned int* wsm = smem_u;                           // 53*1024
    float* zpart = (float*)(smem_u + WSM_ROWS * 1024);    // [2][56][8]
    float* hsm = zpart + 2 * NROWS * 8;                   // [8][256]

    const int tid = threadIdx.x;
    const int cta = blockIdx.x;
    const int u0 = cta * UPC;
    const int nu = min(UPC, HDIM - u0);
    const int lane = tid & 31;
    const int wid = tid >> 5;

    // SMEM weights rows 0..52 (r = g*14+u), compensated-packed, ghost clamp.
    for (int idx = tid; idx < WSM_ROWS * 1024; idx += 256) {
        int r = idx >> 10;
        int c2 = idx & 1023;
        int g = r / UPC;
        int u = r - g * UPC;
        int urow = min(u0 + u, HDIM - 1);
        const float* wrow = Whh + (size_t)(g * HDIM + urow) * HDIM;
        float2 w = *(const float2*)(wrow + 2 * c2);
        wsm[idx] = pack_comp(w.x, w.y);
    }

    // Rows 53 (g3,u11), 54 (g3,u12), 55 (g3,u13) in fp32 registers.
    const int dbase = wid * 256 + lane * 8;
    float w53[8], w54[8], w55[8];
    {
        const float* p53 = Whh + ((size_t)3 * HDIM + min(u0 + 11, HDIM - 1)) * HDIM + dbase;
        const float* p54 = Whh + ((size_t)3 * HDIM + min(u0 + 12, HDIM - 1)) * HDIM + dbase;
        const float* p55 = Whh + ((size_t)3 * HDIM + min(u0 + 13, HDIM - 1)) * HDIM + dbase;
#pragma unroll
        for (int j = 0; j < 8; ++j) { w53[j] = p53[j]; w54[j] = p54[j]; w55[j] = p55[j]; }
    }

    // Gather plan: warp needs producer blocks c0..c1, nv <= 100 vectors.
    const int c0 = (wid * 256) / UPC;
    const int c1 = (wid * 256 + 255) / UPC;
    const int nv = (c1 - c0 + 1) * 5;
    int psrc[4], pdst[4], pnc[4];
    bool pval[4];
#pragma unroll
    for (int p = 0; p < 4; ++p) {
        int v = p * 32 + lane;
        pval[p] = v < nv;
        int vc = pval[p] ? v : 0;
        int b = c0 + vc / 5;
        int vi = vc - (vc / 5) * 5;
        psrc[p] = b * 5 + vi;
        pdst[p] = b * UPC + 3 * vi - wid * 256;
        pnc[p] = (vi == 4) ? 2 : 3;
    }
    __syncthreads();

    const int krev = ((lane >> 4) & 1) | (((lane >> 3) & 1) << 1) | (((lane >> 2) & 1) << 2);
    float cstate = 0.0f;

    for (int t = 0; t < TSEQ; ++t) {
        float xp0 = 0.f, xp1 = 0.f, xp2 = 0.f, xp3 = 0.f;
        if (tid < nu) {
            const float* xp = xproj + (size_t)t * (4 * HDIM) + u0 + tid;
            xp0 = __ldcg(xp);
            xp1 = __ldcg(xp + HDIM);
            xp2 = __ldcg(xp + 2 * HDIM);
            xp3 = __ldcg(xp + 3 * HDIM);
        }
        float* zbuf = zpart + (t & 1) * (NROWS * 8);

        if (t > 0) {
            // poll tagged vectors of step t-1; recheck only pending ones
            const float4* hb = hbuf + (size_t)(t - 1) * (NCTA * 5);
            float4 gv0, gv1, gv2, gv3;
            bool d0 = !pval[0], d1 = !pval[1], d2 = !pval[2], d3 = !pval[3];
            for (;;) {
                if (!d0) { gv0 = ldcg_v4(hb + psrc[0]); d0 = (__float_as_int(gv0.w) == t); }
                if (!d1) { gv1 = ldcg_v4(hb + psrc[1]); d1 = (__float_as_int(gv1.w) == t); }
                if (!d2) { gv2 = ldcg_v4(hb + psrc[2]); d2 = (__float_as_int(gv2.w) == t); }
                if (!d3) { gv3 = ldcg_v4(hb + psrc[3]); d3 = (__float_as_int(gv3.w) == t); }
                if (__all_sync(0xffffffffu, d0 && d1 && d2 && d3)) break;
            }
            float* hw = hsm + wid * 256;
#pragma unroll
            for (int p = 0; p < 4; ++p) {
                if (pval[p]) {
                    float4 g = (p == 0) ? gv0 : (p == 1) ? gv1 : (p == 2) ? gv2 : gv3;
                    int i0 = pdst[p];
                    if ((unsigned)i0 < 256u) hw[i0] = g.x;
                    if ((unsigned)(i0 + 1) < 256u) hw[i0 + 1] = g.y;
                    if (pnc[p] == 3 && (unsigned)(i0 + 2) < 256u) hw[i0 + 2] = g.z;
                }
            }
            __syncwarp();
            float4 ha = *(const float4*)(hw + lane * 8);
            float4 hbv = *(const float4*)(hw + lane * 8 + 4);
            float h0 = ha.x, h1 = ha.y, h2 = ha.z, h3 = ha.w;
            float h4 = hbv.x, h5 = hbv.y, h6 = hbv.z, h7 = hbv.w;

            float acc[NROWS];
            const unsigned int* wbase = wsm + wid * 128 + lane * 4;
#pragma unroll
            for (int r = 0; r < WSM_ROWS; ++r) {
                uint4 w4 = *(const uint4*)(wbase + r * 1024);
                // even = u<<16 (exact bf16); odd = u as-is (compensated)
                float s0 = __uint_as_float(w4.x << 16) * h0;
                float s1 = __uint_as_float(w4.x) * h1;
                s0 = fmaf(__uint_as_float(w4.y << 16), h2, s0);
                s1 = fmaf(__uint_as_float(w4.y), h3, s1);
                s0 = fmaf(__uint_as_float(w4.z << 16), h4, s0);
                s1 = fmaf(__uint_as_float(w4.z), h5, s1);
                s0 = fmaf(__uint_as_float(w4.w << 16), h6, s0);
                s1 = fmaf(__uint_as_float(w4.w), h7, s1);
                acc[r] = s0 + s1;
            }
            {
                float s3 = w53[0] * h0, s4 = w54[0] * h0, s5 = w55[0] * h0;
                s3 = fmaf(w53[1], h1, s3); s4 = fmaf(w54[1], h1, s4); s5 = fmaf(w55[1], h1, s5);
                s3 = fmaf(w53[2], h2, s3); s4 = fmaf(w54[2], h2, s4); s5 = fmaf(w55[2], h2, s5);
                s3 = fmaf(w53[3], h3, s3); s4 = fmaf(w54[3], h3, s4); s5 = fmaf(w55[3], h3, s5);
                s3 = fmaf(w53[4], h4, s3); s4 = fmaf(w54[4], h4, s4); s5 = fmaf(w55[4], h4, s5);
                s3 = fmaf(w53[5], h5, s3); s4 = fmaf(w54[5], h5, s4); s5 = fmaf(w55[5], h5, s5);
                s3 = fmaf(w53[6], h6, s3); s4 = fmaf(w54[6], h6, s4); s5 = fmaf(w55[6], h6, s5);
                s3 = fmaf(w53[7], h7, s3); s4 = fmaf(w54[7], h7, s4); s5 = fmaf(w55[7], h7, s5);
                acc[53] = s3; acc[54] = s4; acc[55] = s5;
            }

            // merge tree: 63 shfl for 56 rows; slot i ends as row 8i+krev
            float ga[28], gb[14], gc[7];
#pragma unroll
            for (int i = 0; i < 28; ++i) ga[i] = merge2(acc[2 * i], acc[2 * i + 1], 16, lane);
#pragma unroll
            for (int i = 0; i < 14; ++i) gb[i] = merge2(ga[2 * i], ga[2 * i + 1], 8, lane);
#pragma unroll
            for (int i = 0; i < 7; ++i)  gc[i] = merge2(gb[2 * i], gb[2 * i + 1], 4, lane);
#pragma unroll
            for (int i = 0; i < 7; ++i) {
                float v = gc[i];
                v += __shfl_xor_sync(0xffffffffu, v, 2);
                v += __shfl_xor_sync(0xffffffffu, v, 1);
                if ((lane & 3) == 0) zbuf[(8 * i + krev) * 8 + wid] = v;
            }
            __syncthreads();
        }

        // gate math + tagged publish (warp 0)
        if (wid == 0) {
            float hv = 0.0f;
            if (lane < nu) {
                float zi = xp0, zf = xp1, zg = xp2, zo = xp3;
                if (t > 0) {
                    const float4* z0 = (const float4*)(zbuf + (0 * UPC + lane) * 8);
                    const float4* z1 = (const float4*)(zbuf + (1 * UPC + lane) * 8);
                    const float4* z2 = (const float4*)(zbuf + (2 * UPC + lane) * 8);
                    const float4* z3 = (const float4*)(zbuf + (3 * UPC + lane) * 8);
                    float4 a, b;
                    a = z0[0]; b = z0[1];
                    zi += (a.x + a.y) + (a.z + a.w) + (b.x + b.y) + (b.z + b.w);
                    a = z1[0]; b = z1[1];
                    zf += (a.x + a.y) + (a.z + a.w) + (b.x + b.y) + (b.z + b.w);
                    a = z2[0]; b = z2[1];
                    zg += (a.x + a.y) + (a.z + a.w) + (b.x + b.y) + (b.z + b.w);
                    a = z3[0]; b = z3[1];
                    zo += (a.x + a.y) + (a.z + a.w) + (b.x + b.y) + (b.z + b.w);
                }
                float ig = fsig(zi);
                float fg = fsig(zf);
                float gg = htanh(zg);
                float og = fsig(zo);
                float c = fg * cstate + ig * gg;
                cstate = c;
                hv = og * htanh(c);
            }
            float pa = __shfl_sync(0xffffffffu, hv, (3 * lane) & 31);
            float pb = __shfl_sync(0xffffffffu, hv, (3 * lane + 1) & 31);
            float pc = __shfl_sync(0xffffffffu, hv, (3 * lane + 2) & 31);
            if (lane < 5)
                stcg_v4(hbuf + ((size_t)t * NCTA + cta) * 5 + lane,
                        pa, pb, pc, __int_as_float(t + 1));
            if (lane < nu)
                __stcg(ys + (size_t)t * HDIM + u0 + lane, hv);
        }
        // no trailing sync: zpart double-buffered by (t&1); any zbuf(t+2)
        // write transitively requires warp 0's step-t publish, which follows
        // its zbuf(t) reads in program order.
    }
}

// ---------------- FC ----------------
__global__ void __launch_bounds__(256) fc_kernel(
    const float* __restrict__ hlast, const float* __restrict__ W,
    const float* __restrict__ bias, float* __restrict__ out)
{
    int o = blockIdx.x * 8 + (threadIdx.x >> 5);
    int lane = threadIdx.x & 31;
    const float* w = W + (size_t)o * HDIM;
    float s = 0.0f;
    for (int k = lane * 4; k < HDIM; k += 128) {
        float4 wv = *(const float4*)(w + k);
        float4 hv = *(const float4*)(hlast + k);
        s += wv.x * hv.x + wv.y * hv.y + wv.z * hv.z + wv.w * hv.w;
    }
    s += __shfl_xor_sync(0xffffffffu, s, 16);
    s += __shfl_xor_sync(0xffffffffu, s, 8);
    s += __shfl_xor_sync(0xffffffffu, s, 4);
    s += __shfl_xor_sync(0xffffffffu, s, 2);
    s += __shfl_xor_sync(0xffffffffu, s, 1);
    if (lane == 0) out[o] = s + bias[o];
}

// ---------------- launch ----------------
extern "C" void kernel_launch(void* const* d_in, const int* in_sizes, int n_in,
                              void* d_out, int out_size)
{
    const float* x    = (const float*)d_in[0];
    const float* Wih0 = (const float*)d_in[1];
    const float* Whh0 = (const float*)d_in[2];
    const float* bih0 = (const float*)d_in[3];
    const float* bhh0 = (const float*)d_in[4];
    const float* Wih1 = (const float*)d_in[5];
    const float* Whh1 = (const float*)d_in[6];
    const float* bih1 = (const float*)d_in[7];
    const float* bhh1 = (const float*)d_in[8];
    const float* fcw  = (const float*)d_in[9];
    const float* fcb  = (const float*)d_in[10];
    float* out = (float*)d_out;

    float *xproj, *ys0, *ys1;
    float4 *hb0, *hb1;
    cudaGetSymbolAddress((void**)&xproj, g_xproj);
    cudaGetSymbolAddress((void**)&ys0, g_ys0);
    cudaGetSymbolAddress((void**)&ys1, g_ys1);
    cudaGetSymbolAddress((void**)&hb0, g_hbuf0);
    cudaGetSymbolAddress((void**)&hb1, g_hbuf1);

    cudaFuncSetAttribute(lstm_layer_kernel,
                         cudaFuncAttributeMaxDynamicSharedMemorySize, SMEM_BYTES);

    zero_hbuf_kernel<<<592, 256>>>();

    dim3 ggrid((4 * HDIM) / BN, TSEQ / BM);
    gemm_bias_kernel<<<ggrid, 256>>>(x, Wih0, bih0, bhh0, xproj, TSEQ, 4 * HDIM, DDIM);
    lstm_layer_kernel<<<NCTA, 256, SMEM_BYTES>>>(Whh0, xproj, ys0, hb0);
    gemm_bias_kernel<<<ggrid, 256>>>(ys0, Wih1, bih1, bhh1, xproj, TSEQ, 4 * HDIM, HDIM);
    lstm_layer_kernel<<<NCTA, 256, SMEM_BYTES>>>(Whh1, xproj, ys1, hb1);
    fc_kernel<<<ODIM / 8, 256>>>(ys1 + (size_t)(TSEQ - 1) * HDIM, fcw, fcb, out);
}

// round 12
// speedup vs baseline: 1.3572x; 1.0993x over previous
#include <cuda_runtime.h>
#include <cuda_bf16.h>

#define TSEQ 2048
#define HDIM 2048
#define DDIM 512
#define ODIM 512
#define NCTA 147
#define UPC  14
#define NROWS 56
#define WSM_ROWS 54
// SMEM: 54*1024 u32 weights + zpart[56*8] + hsm[8*256] = 231168 <= 232448
#define SMEM_BYTES (WSM_ROWS * 1024 * 4 + NROWS * 8 * 4 + 8 * 256 * 4)

// ---------------- scratch (device globals; no allocation) ----------------
__device__ float  g_xproj[(size_t)TSEQ * 4 * HDIM];
__device__ float  g_ys0[(size_t)TSEQ * HDIM];
__device__ float  g_ys1[(size_t)TSEQ * HDIM];
__device__ float4 g_hbuf0[(size_t)TSEQ * NCTA * 5];   // {h,h,h,tag}
__device__ float4 g_hbuf1[(size_t)TSEQ * NCTA * 5];

__global__ void zero_hbuf_kernel() {
    size_t n = (size_t)TSEQ * NCTA * 5;
    float4 z = make_float4(0.f, 0.f, 0.f, 0.f);
    for (size_t i = blockIdx.x * blockDim.x + threadIdx.x; i < n;
         i += (size_t)gridDim.x * blockDim.x) {
        g_hbuf0[i] = z;
        g_hbuf1[i] = z;
    }
}

// ---------------- helpers ----------------
__device__ __forceinline__ float4 ldcg_v4(const float4* p) {
    float4 v;
    asm volatile("ld.global.cg.v4.f32 {%0,%1,%2,%3}, [%4];"
                 : "=f"(v.x), "=f"(v.y), "=f"(v.z), "=f"(v.w) : "l"(p));
    return v;
}
__device__ __forceinline__ void stcg_v4(float4* p, float a, float b, float c, float d) {
    asm volatile("st.global.cg.v4.f32 [%0], {%1,%2,%3,%4};"
                 :: "l"(p), "f"(a), "f"(b), "f"(c), "f"(d) : "memory");
}
// HW tanh (MUFU.TANH) gate math — numerics validated in R8/R11 (rel_err 3.91e-4)
__device__ __forceinline__ float htanh(float x) {
    float r;
    asm("tanh.approx.f32 %0, %1;" : "=f"(r) : "f"(x));
    return r;
}
__device__ __forceinline__ float fsig(float x) {
    return fmaf(0.5f, htanh(0.5f * x), 0.5f);
}
__device__ __forceinline__ float merge2(float a, float b, int m, int lane) {
    bool hi = (lane & m) != 0;
    float mine = hi ? b : a;
    float theirs = hi ? a : b;
    return mine + __shfl_xor_sync(0xffffffffu, theirs, m);
}
// Compensated pack: low 16 = bf16(w_even); whole u32 read as f32 is the
// nearest value to w_odd on lattice {k*2^16 + lo} (error <= half bf16 ulp).
__device__ __forceinline__ unsigned pack_comp(float we, float wo) {
    unsigned lo = (unsigned)__bfloat16_as_ushort(__float2bfloat16_rn(we));
    unsigned ob = __float_as_uint(wo);
    unsigned hi = (ob >= 0x10000u) ? ((ob - lo + 0x8000u) >> 16) : (ob >> 16);
    return (hi << 16) | lo;
}

// ---------------- GEMM: C[m][n] = sum_k A[m][k]*B[n][k] + b1[n] + b2[n] ----
#define BM 128
#define BN 128
#define BK 16

__global__ void __launch_bounds__(256, 2) gemm_bias_kernel(
    const float* __restrict__ A, const float* __restrict__ B,
    const float* __restrict__ bias1, const float* __restrict__ bias2,
    float* __restrict__ C, int M, int N, int K)
{
    __shared__ float As[BK][BM + 4];
    __shared__ float Bs[BK][BN + 4];
    const int tid = threadIdx.x;
    const int tx = tid & 15;
    const int ty = tid >> 4;
    const int m0 = blockIdx.y * BM;
    const int n0 = blockIdx.x * BN;
    const int lrow = tid >> 2;
    const int lk4  = (tid & 3) * 4;

    const float* Aptr0 = A + (size_t)(m0 + lrow) * K + lk4;
    const float* Aptr1 = A + (size_t)(m0 + lrow + 64) * K + lk4;
    const float* Bptr0 = B + (size_t)(n0 + lrow) * K + lk4;
    const float* Bptr1 = B + (size_t)(n0 + lrow + 64) * K + lk4;

    float4 ra0 = *(const float4*)(Aptr0);
    float4 ra1 = *(const float4*)(Aptr1);
    float4 rb0 = *(const float4*)(Bptr0);
    float4 rb1 = *(const float4*)(Bptr1);

    float acc[8][8];
#pragma unroll
    for (int i = 0; i < 8; ++i)
#pragma unroll
        for (int j = 0; j < 8; ++j) acc[i][j] = 0.0f;

    for (int k0 = 0; k0 < K; k0 += BK) {
        As[lk4 + 0][lrow] = ra0.x; As[lk4 + 1][lrow] = ra0.y;
        As[lk4 + 2][lrow] = ra0.z; As[lk4 + 3][lrow] = ra0.w;
        As[lk4 + 0][lrow + 64] = ra1.x; As[lk4 + 1][lrow + 64] = ra1.y;
        As[lk4 + 2][lrow + 64] = ra1.z; As[lk4 + 3][lrow + 64] = ra1.w;
        Bs[lk4 + 0][lrow] = rb0.x; Bs[lk4 + 1][lrow] = rb0.y;
        Bs[lk4 + 2][lrow] = rb0.z; Bs[lk4 + 3][lrow] = rb0.w;
        Bs[lk4 + 0][lrow + 64] = rb1.x; Bs[lk4 + 1][lrow + 64] = rb1.y;
        Bs[lk4 + 2][lrow + 64] = rb1.z; Bs[lk4 + 3][lrow + 64] = rb1.w;
        __syncthreads();

        if (k0 + BK < K) {
            ra0 = *(const float4*)(Aptr0 + k0 + BK);
            ra1 = *(const float4*)(Aptr1 + k0 + BK);
            rb0 = *(const float4*)(Bptr0 + k0 + BK);
            rb1 = *(const float4*)(Bptr1 + k0 + BK);
        }

#pragma unroll
        for (int kk = 0; kk < BK; ++kk) {
            float4 a0 = *(const float4*)&As[kk][ty * 4];
            float4 a1 = *(const float4*)&As[kk][64 + ty * 4];
            float4 b0 = *(const float4*)&Bs[kk][tx * 4];
            float4 b1 = *(const float4*)&Bs[kk][64 + tx * 4];
            float av[8] = {a0.x, a0.y, a0.z, a0.w, a1.x, a1.y, a1.z, a1.w};
            float bv[8] = {b0.x, b0.y, b0.z, b0.w, b1.x, b1.y, b1.z, b1.w};
#pragma unroll
            for (int i = 0; i < 8; ++i)
#pragma unroll
                for (int j = 0; j < 8; ++j)
                    acc[i][j] = fmaf(av[i], bv[j], acc[i][j]);
        }
        __syncthreads();
    }

    float bs[8];
#pragma unroll
    for (int j = 0; j < 8; ++j) {
        int n = n0 + ((j < 4) ? (tx * 4 + j) : (64 + tx * 4 + (j - 4)));
        bs[j] = bias1[n] + bias2[n];
    }
#pragma unroll
    for (int i = 0; i < 8; ++i) {
        int m = m0 + ((i < 4) ? (ty * 4 + i) : (64 + ty * 4 + (i - 4)));
        float4 v0 = make_float4(acc[i][0] + bs[0], acc[i][1] + bs[1],
                                acc[i][2] + bs[2], acc[i][3] + bs[3]);
        float4 v1 = make_float4(acc[i][4] + bs[4], acc[i][5] + bs[5],
                                acc[i][6] + bs[6], acc[i][7] + bs[7]);
        *(float4*)(C + (size_t)m * N + n0 + tx * 4) = v0;
        *(float4*)(C + (size_t)m * N + n0 + 64 + tx * 4) = v1;
    }
}

// ---------------- persistent LSTM recurrence (tagged publish) -------------
__global__ void __launch_bounds__(256, 1) lstm_layer_kernel(
    const float* __restrict__ Whh, const float* __restrict__ xproj,
    float* __restrict__ ys, float4* __restrict__ hbuf)
{
    extern __shared__ unsigned int smem_u[];
    unsigned int* wsm = smem_u;                           // 54*1024
    float* zpart = (float*)(smem_u + WSM_ROWS * 1024);    // [56][8], 16B rows
    float* hsm = zpart + NROWS * 8;                       // [8][256]

    const int tid = threadIdx.x;
    const int cta = blockIdx.x;
    const int u0 = cta * UPC;
    const int nu = min(UPC, HDIM - u0);
    const int lane = tid & 31;
    const int wid = tid >> 5;

    // SMEM weights rows 0..53 (r = g*14+u), compensated-packed, ghost clamp.
    for (int idx = tid; idx < WSM_ROWS * 1024; idx += 256) {
        int r = idx >> 10;
        int c2 = idx & 1023;
        int g = r / UPC;
        int u = r - g * UPC;
        int urow = min(u0 + u, HDIM - 1);
        const float* wrow = Whh + (size_t)(g * HDIM + urow) * HDIM;
        float2 w = *(const float2*)(wrow + 2 * c2);
        wsm[idx] = pack_comp(w.x, w.y);
    }

    // Rows 54 (g3,u12), 55 (g3,u13) in fp32 registers (k-slice per thread).
    const int dbase = wid * 256 + lane * 8;
    float w54[8], w55[8];
    {
        const float* p54 = Whh + ((size_t)3 * HDIM + min(u0 + 12, HDIM - 1)) * HDIM + dbase;
        const float* p55 = Whh + ((size_t)3 * HDIM + min(u0 + 13, HDIM - 1)) * HDIM + dbase;
#pragma unroll
        for (int j = 0; j < 8; ++j) { w54[j] = p54[j]; w55[j] = p55[j]; }
    }

    // Gather plan: warp needs producer blocks c0..c1, nv <= 100 vectors.
    const int c0 = (wid * 256) / UPC;
    const int c1 = (wid * 256 + 255) / UPC;
    const int nv = (c1 - c0 + 1) * 5;
    int psrc[4], pdst[4], pnc[4];
    bool pval[4];
#pragma unroll
    for (int p = 0; p < 4; ++p) {
        int v = p * 32 + lane;
        pval[p] = v < nv;
        int vc = pval[p] ? v : 0;
        int b = c0 + vc / 5;
        int vi = vc - (vc / 5) * 5;
        psrc[p] = b * 5 + vi;
        pdst[p] = b * UPC + 3 * vi - wid * 256;
        pnc[p] = (vi == 4) ? 2 : 3;
    }
    __syncthreads();

    const int krev = ((lane >> 4) & 1) | (((lane >> 3) & 1) << 1) | (((lane >> 2) & 1) << 2);
    float cstate = 0.0f;

    for (int t = 0; t < TSEQ; ++t) {
        float xp0 = 0.f, xp1 = 0.f, xp2 = 0.f, xp3 = 0.f;
        if (tid < nu) {
            const float* xp = xproj + (size_t)t * (4 * HDIM) + u0 + tid;
            xp0 = __ldcg(xp);
            xp1 = __ldcg(xp + HDIM);
            xp2 = __ldcg(xp + 2 * HDIM);
            xp3 = __ldcg(xp + 3 * HDIM);
        }

        if (t > 0) {
            // poll tagged vectors of step t-1; recheck only pending ones
            const float4* hb = hbuf + (size_t)(t - 1) * (NCTA * 5);
            float4 gv0, gv1, gv2, gv3;
            bool d0 = !pval[0], d1 = !pval[1], d2 = !pval[2], d3 = !pval[3];
            for (;;) {
                if (!d0) { gv0 = ldcg_v4(hb + psrc[0]); d0 = (__float_as_int(gv0.w) == t); }
                if (!d1) { gv1 = ldcg_v4(hb + psrc[1]); d1 = (__float_as_int(gv1.w) == t); }
                if (!d2) { gv2 = ldcg_v4(hb + psrc[2]); d2 = (__float_as_int(gv2.w) == t); }
                if (!d3) { gv3 = ldcg_v4(hb + psrc[3]); d3 = (__float_as_int(gv3.w) == t); }
                if (__all_sync(0xffffffffu, d0 && d1 && d2 && d3)) break;
            }
            float* hw = hsm + wid * 256;
#pragma unroll
            for (int p = 0; p < 4; ++p) {
                if (pval[p]) {
                    float4 g = (p == 0) ? gv0 : (p == 1) ? gv1 : (p == 2) ? gv2 : gv3;
                    int i0 = pdst[p];
                    if ((unsigned)i0 < 256u) hw[i0] = g.x;
                    if ((unsigned)(i0 + 1) < 256u) hw[i0 + 1] = g.y;
                    if (pnc[p] == 3 && (unsigned)(i0 + 2) < 256u) hw[i0 + 2] = g.z;
                }
            }
            __syncwarp();
            float4 ha = *(const float4*)(hw + lane * 8);
            float4 hbv = *(const float4*)(hw + lane * 8 + 4);
            float h0 = ha.x, h1 = ha.y, h2 = ha.z, h3 = ha.w;
            float h4 = hbv.x, h5 = hbv.y, h6 = hbv.z, h7 = hbv.w;

            float acc[NROWS];
            const unsigned int* wbase = wsm + wid * 128 + lane * 4;
#pragma unroll
            for (int r = 0; r < WSM_ROWS; ++r) {
                uint4 w4 = *(const uint4*)(wbase + r * 1024);
                // even = u<<16 (exact bf16); odd = u as-is (compensated)
                float s0 = __uint_as_float(w4.x << 16) * h0;
                float s1 = __uint_as_float(w4.x) * h1;
                s0 = fmaf(__uint_as_float(w4.y << 16), h2, s0);
                s1 = fmaf(__uint_as_float(w4.y), h3, s1);
                s0 = fmaf(__uint_as_float(w4.z << 16), h4, s0);
                s1 = fmaf(__uint_as_float(w4.z), h5, s1);
                s0 = fmaf(__uint_as_float(w4.w << 16), h6, s0);
                s1 = fmaf(__uint_as_float(w4.w), h7, s1);
                acc[r] = s0 + s1;
            }
            {
                float s4 = w54[0] * h0, s5 = w55[0] * h0;
                s4 = fmaf(w54[1], h1, s4); s5 = fmaf(w55[1], h1, s5);
                s4 = fmaf(w54[2], h2, s4); s5 = fmaf(w55[2], h2, s5);
                s4 = fmaf(w54[3], h3, s4); s5 = fmaf(w55[3], h3, s5);
                s4 = fmaf(w54[4], h4, s4); s5 = fmaf(w55[4], h4, s5);
                s4 = fmaf(w54[5], h5, s4); s5 = fmaf(w55[5], h5, s5);
                s4 = fmaf(w54[6], h6, s4); s5 = fmaf(w55[6], h6, s5);
                s4 = fmaf(w54[7], h7, s4); s5 = fmaf(w55[7], h7, s5);
                acc[54] = s4; acc[55] = s5;
            }

            // merge tree: 63 shfl for 56 rows; slot i ends as row 8i+krev
            float ga[28], gb[14], gc[7];
#pragma unroll
            for (int i = 0; i < 28; ++i) ga[i] = merge2(acc[2 * i], acc[2 * i + 1], 16, lane);
#pragma unroll
            for (int i = 0; i < 14; ++i) gb[i] = merge2(ga[2 * i], ga[2 * i + 1], 8, lane);
#pragma unroll
            for (int i = 0; i < 7; ++i)  gc[i] = merge2(gb[2 * i], gb[2 * i + 1], 4, lane);
#pragma unroll
            for (int i = 0; i < 7; ++i) {
                float v = gc[i];
                v += __shfl_xor_sync(0xffffffffu, v, 2);
                v += __shfl_xor_sync(0xffffffffu, v, 1);
                if ((lane & 3) == 0) zpart[(8 * i + krev) * 8 + wid] = v;
            }
            __syncthreads();
        }

        // gate math + tagged publish (warp 0)
        if (wid == 0) {
            float hv = 0.0f;
            if (lane < nu) {
                float zi = xp0, zf = xp1, zg = xp2, zo = xp3;
                if (t > 0) {
                    const float4* z0 = (const float4*)(zpart + (0 * UPC + lane) * 8);
                    const float4* z1 = (const float4*)(zpart + (1 * UPC + lane) * 8);
                    const float4* z2 = (const float4*)(zpart + (2 * UPC + lane) * 8);
                    const float4* z3 = (const float4*)(zpart + (3 * UPC + lane) * 8);
                    float4 a, b;
                    a = z0[0]; b = z0[1];
                    zi += (a.x + a.y) + (a.z + a.w) + (b.x + b.y) + (b.z + b.w);
                    a = z1[0]; b = z1[1];
                    zf += (a.x + a.y) + (a.z + a.w) + (b.x + b.y) + (b.z + b.w);
                    a = z2[0]; b = z2[1];
                    zg += (a.x + a.y) + (a.z + a.w) + (b.x + b.y) + (b.z + b.w);
                    a = z3[0]; b = z3[1];
                    zo += (a.x + a.y) + (a.z + a.w) + (b.x + b.y) + (b.z + b.w);
                }
                float ig = fsig(zi);
                float fg = fsig(zf);
                float gg = htanh(zg);
                float og = fsig(zo);
                float c = fg * cstate + ig * gg;
                cstate = c;
                hv = og * htanh(c);
            }
            float pa = __shfl_sync(0xffffffffu, hv, (3 * lane) & 31);
            float pb = __shfl_sync(0xffffffffu, hv, (3 * lane + 1) & 31);
            float pc = __shfl_sync(0xffffffffu, hv, (3 * lane + 2) & 31);
            if (lane < 5)
                stcg_v4(hbuf + ((size_t)t * NCTA + cta) * 5 + lane,
                        pa, pb, pc, __int_as_float(t + 1));
            if (lane < nu)
                __stcg(ys + (size_t)t * HDIM + u0 + lane, hv);
        }
        __syncthreads();   // poll throttle + zpart/hsm reuse fence (load-bearing)
    }
}

// ---------------- FC ----------------
__global__ void __launch_bounds__(256) fc_kernel(
    const float* __restrict__ hlast, const float* __restrict__ W,
    const float* __restrict__ bias, float* __restrict__ out)
{
    int o = blockIdx.x * 8 + (threadIdx.x >> 5);
    int lane = threadIdx.x & 31;
    const float* w = W + (size_t)o * HDIM;
    float s = 0.0f;
    for (int k = lane * 4; k < HDIM; k += 128) {
        float4 wv = *(const float4*)(w + k);
        float4 hv = *(const float4*)(hlast + k);
        s += wv.x * hv.x + wv.y * hv.y + wv.z * hv.z + wv.w * hv.w;
    }
    s += __shfl_xor_sync(0xffffffffu, s, 16);
    s += __shfl_xor_sync(0xffffffffu, s, 8);
    s += __shfl_xor_sync(0xffffffffu, s, 4);
    s += __shfl_xor_sync(0xffffffffu, s, 2);
    s += __shfl_xor_sync(0xffffffffu, s, 1);
    if (lane == 0) out[o] = s + bias[o];
}

// ---------------- launch ----------------
extern "C" void kernel_launch(void* const* d_in, const int* in_sizes, int n_in,
                              void* d_out, int out_size)
{
    const float* x    = (const float*)d_in[0];
    const float* Wih0 = (const float*)d_in[1];
    const float* Whh0 = (const float*)d_in[2];
    const float* bih0 = (const float*)d_in[3];
    const float* bhh0 = (const float*)d_in[4];
    const float* Wih1 = (const float*)d_in[5];
    const float* Whh1 = (const float*)d_in[6];
    const float* bih1 = (const float*)d_in[7];
    const float* bhh1 = (const float*)d_in[8];
    const float* fcw  = (const float*)d_in[9];
    const float* fcb  = (const float*)d_in[10];
    float* out = (float*)d_out;

    float *xproj, *ys0, *ys1;
    float4 *hb0, *hb1;
    cudaGetSymbolAddress((void**)&xproj, g_xproj);
    cudaGetSymbolAddress((void**)&ys0, g_ys0);
    cudaGetSymbolAddress((void**)&ys1, g_ys1);
    cudaGetSymbolAddress((void**)&hb0, g_hbuf0);
    cudaGetSymbolAddress((void**)&hb1, g_hbuf1);

    cudaFuncSetAttribute(lstm_layer_kernel,
                         cudaFuncAttributeMaxDynamicSharedMemorySize, SMEM_BYTES);

    zero_hbuf_kernel<<<592, 256>>>();

    dim3 ggrid((4 * HDIM) / BN, TSEQ / BM);
    gemm_bias_kernel<<<ggrid, 256>>>(x, Wih0, bih0, bhh0, xproj, TSEQ, 4 * HDIM, DDIM);
    lstm_layer_kernel<<<NCTA, 256, SMEM_BYTES>>>(Whh0, xproj, ys0, hb0);
    gemm_bias_kernel<<<ggrid, 256>>>(ys0, Wih1, bih1, bhh1, xproj, TSEQ, 4 * HDIM, HDIM);
    lstm_layer_kernel<<<NCTA, 256, SMEM_BYTES>>>(Whh1, xproj, ys1, hb1);
    fc_kernel<<<ODIM / 8, 256>>>(ys1 + (size_t)(TSEQ - 1) * HDIM, fcw, fcb, out);
}